// round 12
// baseline (speedup 1.0000x reference)
#include <cuda_runtime.h>
#include <cstdint>

#define BATCH   16384
#define NCONDS  50
#define EMB_DIM 64
#define IN_ROW  (1 + NCONDS)             // 51 int32 per batch row
#define OUT_ROW ((1 + NCONDS) * EMB_DIM) // 3264 floats = 13056 B per row
#define PF      4                        // prefetch depth (stages)
#define NSTAGE  (NCONDS / 2)             // 25 stages, 2 conds per stage
#define WPB     2                        // warps per block (smem-limited)

__device__ __forceinline__ uint32_t smem_u32(const void* p) {
    uint32_t a;
    asm("{ .reg .u64 t; cvta.to.shared.u64 t, %1; cvt.u32.u64 %0, t; }"
        : "=r"(a) : "l"(p));
    return a;
}

// One warp per batch row. Results staged in shared memory (STS.128, cheap
// LSU issue) and flushed with a single cp.async.bulk shared->global per row,
// moving the 214 MB write stream off the STG path (12 cyc/instr) onto TMA.
__global__ void __launch_bounds__(WPB * 32)
cond_filter_kernel(const int* __restrict__ inp,
                   const float* __restrict__ table,
                   float* __restrict__ out)
{
    __shared__ __align__(16) float sbuf[WPB * OUT_ROW];   // 26112 B

    const int warp = (blockIdx.x * blockDim.x + threadIdx.x) >> 5;
    const int lane = threadIdx.x & 31;
    if (warp >= BATCH) return;

    const int hl   = lane & 15;   // lane within half-warp
    const int half = lane >> 4;   // which half-warp (0/1)

    const int* __restrict__ row = inp + (size_t)warp * IN_ROW;
    float* __restrict__ my = sbuf + (threadIdx.x >> 5) * OUT_ROW;

    // ---- Prologue: start PF condition gathers immediately ----
    float4 ring[PF];
    #pragma unroll
    for (int p = 0; p < PF; p++) {
        const int cidx = __ldg(row + 1 + 2 * p + half);
        ring[p] = *reinterpret_cast<const float4*>(
            table + (size_t)cidx * EMB_DIM + hl * 4);
    }

    // ---- Event: raw copy into smem staging + normalize in registers ----
    const int eidx = __ldg(row);
    const float4 ev = *reinterpret_cast<const float4*>(
        table + (size_t)eidx * EMB_DIM + hl * 4);
    if (half == 0)
        *reinterpret_cast<float4*>(my + hl * 4) = ev;

    float ss = ev.x * ev.x + ev.y * ev.y + ev.z * ev.z + ev.w * ev.w;
    #pragma unroll
    for (int o = 8; o; o >>= 1)
        ss += __shfl_xor_sync(0xffffffffu, ss, o);   // within half-warp
    const float einv = rsqrtf(ss);
    const float4 en = make_float4(ev.x * einv, ev.y * einv,
                                  ev.z * einv, ev.w * einv);

    // ---- Stages: consume s, prefetch s+PF, stage result in smem ----
    #pragma unroll
    for (int s = 0; s < NSTAGE; s++) {
        const float4 cv = ring[s % PF];
        if (s + PF < NSTAGE) {
            const int cidx = __ldg(row + 1 + 2 * (s + PF) + half);
            ring[s % PF] = *reinterpret_cast<const float4*>(
                table + (size_t)cidx * EMB_DIM + hl * 4);
        }

        float s2 = cv.x * cv.x + cv.y * cv.y + cv.z * cv.z + cv.w * cv.w;
        float dt = cv.x * en.x + cv.y * en.y + cv.z * en.z + cv.w * en.w;
        #pragma unroll
        for (int o = 8; o; o >>= 1) {
            s2 += __shfl_xor_sync(0xffffffffu, s2, o);
            dt += __shfl_xor_sync(0xffffffffu, dt, o);
        }
        const float cinv  = rsqrtf(s2);
        const float scale = dt * cinv * cinv;   // cond_nrm * score folded

        *reinterpret_cast<float4*>(
            my + (size_t)(1 + 2 * s + half) * EMB_DIM + hl * 4) =
            make_float4(cv.x * scale, cv.y * scale, cv.z * scale, cv.w * scale);
    }

    // ---- Epilogue: one bulk TMA store of the whole 13056-B row ----
    __syncwarp();
    if (lane == 0) {
        asm volatile("fence.proxy.async.shared::cta;" ::: "memory");
        const uint32_t saddr = smem_u32(my);
        float* gptr = out + (size_t)warp * OUT_ROW;
        asm volatile(
            "cp.async.bulk.global.shared::cta.bulk_group [%0], [%1], %2;"
            :: "l"(gptr), "r"(saddr), "r"((int)(OUT_ROW * sizeof(float)))
            : "memory");
        asm volatile("cp.async.bulk.commit_group;" ::: "memory");
        asm volatile("cp.async.bulk.wait_group 0;" ::: "memory");
    }
}

extern "C" void kernel_launch(void* const* d_in, const int* in_sizes, int n_in,
                              void* d_out, int out_size)
{
    const int*   inp   = (const int*)d_in[0];     // (16384, 51) int32
    const float* table = (const float*)d_in[1];   // (100002, 64) float32
    float*       out   = (float*)d_out;           // (16384, 3264) float32

    const int threads = WPB * 32;                 // 64 threads = 2 warps
    const int blocks  = BATCH / WPB;              // 8192 blocks
    cond_filter_kernel<<<blocks, threads>>>(inp, table, out);
}

// round 14
// speedup vs baseline: 1.5329x; 1.5329x over previous
#include <cuda_runtime.h>
#include <cstdint>

#define BATCH   16384
#define NCONDS  50
#define EMB_DIM 64
#define IN_ROW  (1 + NCONDS)             // 51 int32 per batch row
#define OUT_ROW ((1 + NCONDS) * EMB_DIM) // 3264 floats per batch row
#define PF      4                        // software-pipeline depth
#define NSTAGE  (NCONDS / 2)             // 25 stages, 2 conds per stage

// Single-pass, one warp per batch row; each half-warp (16 lanes x float4)
// owns one condition per stage. PF-deep register prefetch ring; streaming
// (evict-first) stores; fused 5-shfl dual reduction (s2 + dt together).
__global__ void __launch_bounds__(256, 8)
cond_filter_kernel(const int* __restrict__ inp,
                   const float* __restrict__ table,
                   float* __restrict__ out)
{
    const int warp = (blockIdx.x * blockDim.x + threadIdx.x) >> 5;
    const int lane = threadIdx.x & 31;
    if (warp >= BATCH) return;

    const int hl   = lane & 15;          // lane within half-warp
    const int half = lane >> 4;          // which half-warp (0/1)
    const bool hi8 = (lane & 8) != 0;    // high 8-lane subgroup of the half

    const int* __restrict__ row  = inp + (size_t)warp * IN_ROW;
    float* __restrict__     orow = out + (size_t)warp * OUT_ROW;

    // ---- Prologue: start PF condition gathers immediately ----
    float4 ring[PF];
    #pragma unroll
    for (int p = 0; p < PF; p++) {
        const int cidx = __ldg(row + 1 + 2 * p + half);
        ring[p] = *reinterpret_cast<const float4*>(
            table + (size_t)cidx * EMB_DIM + hl * 4);
    }

    // ---- Event: raw copy out + normalize in registers ----
    const int eidx = __ldg(row);
    const float4 ev = *reinterpret_cast<const float4*>(
        table + (size_t)eidx * EMB_DIM + hl * 4);
    if (half == 0)
        __stcs(reinterpret_cast<float4*>(orow + hl * 4), ev);

    float ss = ev.x * ev.x + ev.y * ev.y + ev.z * ev.z + ev.w * ev.w;
    #pragma unroll
    for (int o = 8; o; o >>= 1)
        ss += __shfl_xor_sync(0xffffffffu, ss, o);   // within half-warp
    const float einv = rsqrtf(ss);
    const float4 en = make_float4(ev.x * einv, ev.y * einv,
                                  ev.z * einv, ev.w * einv);

    // ---- Stages: consume s, prefetch s+PF ----
    float* __restrict__ crow = orow + EMB_DIM;
    #pragma unroll
    for (int s = 0; s < NSTAGE; s++) {
        const float4 cv = ring[s % PF];
        if (s + PF < NSTAGE) {
            const int cidx = __ldg(row + 1 + 2 * (s + PF) + half);
            ring[s % PF] = *reinterpret_cast<const float4*>(
                table + (size_t)cidx * EMB_DIM + hl * 4);
        }

        float s2 = cv.x * cv.x + cv.y * cv.y + cv.z * cv.z + cv.w * cv.w;
        float dt = cv.x * en.x + cv.y * en.y + cv.z * en.z + cv.w * en.w;

        // Fused dual reduction over the 16-lane half-warp (5 SHFLs):
        //  1) xor-8 exchange: low 8 lanes accumulate dt, high 8 accumulate s2
        const float mine  = hi8 ? s2 : dt;             // kind this lane keeps
        const float other = hi8 ? dt : s2;             // kind it sends away
        float z = mine + __shfl_xor_sync(0xffffffffu, other, 8);
        //  2) 3-step butterfly within each 8-lane subgroup reduces z fully
        #pragma unroll
        for (int o = 4; o; o >>= 1)
            z += __shfl_xor_sync(0xffffffffu, z, o);
        //  3) one xor-8 swap hands each lane the other kind
        const float zb = __shfl_xor_sync(0xffffffffu, z, 8);
        const float dts = hi8 ? zb : z;                // full dot
        const float s2s = hi8 ? z  : zb;               // full sum-of-squares

        const float cinv  = rsqrtf(s2s);
        // filtered = cond_nrm * score = cv * (dt * cinv^2)
        const float scale = dts * cinv * cinv;

        __stcs(reinterpret_cast<float4*>(
                   crow + (size_t)(2 * s + half) * EMB_DIM + hl * 4),
               make_float4(cv.x * scale, cv.y * scale, cv.z * scale, cv.w * scale));
    }
}

extern "C" void kernel_launch(void* const* d_in, const int* in_sizes, int n_in,
                              void* d_out, int out_size)
{
    const int*   inp   = (const int*)d_in[0];     // (16384, 51) int32
    const float* table = (const float*)d_in[1];   // (100002, 64) float32
    float*       out   = (float*)d_out;           // (16384, 3264) float32

    const int threads = 256;                 // 8 warps/block
    const int total_threads = BATCH * 32;    // one warp per row
    const int blocks = (total_threads + threads - 1) / threads;
    cond_filter_kernel<<<blocks, threads>>>(inp, table, out);
}